// round 11
// baseline (speedup 1.0000x reference)
#include <cuda_runtime.h>
#include <math.h>

#define EMB 256
#define NH1 32
#define NH2 16
#define MAXDAGS 1024
#define MAXOPS  102400
#define BM 128
#define KC 32
#define SXW 34          // x-tile row stride in words (even => conflict-free broadcast LDS.64)
#define SHP 34          // h-pre row stride
#define GRID_OPS 296    // 2 blocks/SM * 148 SMs guaranteed resident

// ---------------- scratch (device globals; no allocation allowed) ----------------
__device__ int   g_offsets[MAXDAGS + 1];
__device__ int   g_dagid[MAXOPS];
__device__ float g_yzop[MAXDAGS * NH1];   // y-part only (z added in tail)
__device__ float g_prpre[MAXDAGS * NH1];  // y-part only
__device__ float g_zop[NH1];
__device__ float g_zpr[NH1];
__device__ float g_partial[1024];
__device__ float g_w1i[EMB * NH1];        // W1 interleaved: [kp][half][jl][4] (see k_pre)
__device__ float g_inv;
__device__ unsigned int g_counter;
__device__ volatile unsigned int g_relflag;
__device__ volatile unsigned int g_scanflag;

// ---------------- f32x2 helpers ----------------
__device__ __forceinline__ void ffma2(unsigned long long& d, unsigned long long a, unsigned long long b) {
    asm("fma.rn.f32x2 %0, %1, %2, %0;" : "+l"(d) : "l"(a), "l"(b));
}
__device__ __forceinline__ unsigned long long pack2(float x, float y) {
    unsigned long long r;
    asm("mov.b64 %0, {%1,%2};" : "=l"(r) : "f"(x), "f"(y));
    return r;
}
__device__ __forceinline__ float2 unpack2(unsigned long long v) {
    float2 r;
    asm("mov.b64 {%0,%1}, %2;" : "=f"(r.x), "=f"(r.y) : "l"(v));
    return r;
}
__device__ __forceinline__ unsigned int smem_u32(const void* p) {
    return (unsigned int)__cvta_generic_to_shared(p);
}

// ================= k_pre: ALL preprocessing in one wide parallel launch =================
// block 0            : scan + resets (+ sets g_scanflag)
// block 1            : z-dots
// blocks [2,10)      : W1 interleave
// blocks [10,10+nbY) : y-dots op branch (16 dags/block)
// next nbY           : y-dots pr branch
// next nbF           : dagid fill (spins on g_scanflag)
__global__ void __launch_bounds__(512) k_pre(
    const int* __restrict__ num_ops, const float* __restrict__ z,
    const float* __restrict__ y,
    const float* __restrict__ opW1, const float* __restrict__ prW1,
    int D, int N, int nbY, int nbF)
{
    __shared__ float sy[16 * EMB];   // 16 KB (aliased: scan buffer / offsets)
    __shared__ float sw[64 * NH1];   // 8 KB
    int t = threadIdx.x;
    int b = blockIdx.x;

    if (b == 0) {
        if (t == 0) { g_counter = 0u; g_relflag = 0u; }
        int* s = reinterpret_cast<int*>(sy);
        for (int i = t; i < 1024; i += 512) s[i] = (i < D) ? num_ops[i] : 0;
        __syncthreads();
        for (int off = 1; off < 1024; off <<= 1) {
            int i0 = t, i1 = t + 512;
            int v0 = (i0 >= off) ? s[i0 - off] : 0;
            int v1 = (i1 >= off) ? s[i1 - off] : 0;
            __syncthreads();
            s[i0] += v0; s[i1] += v1;
            __syncthreads();
        }
        for (int i = t; i < 1024; i += 512) g_offsets[i + 1] = s[i];
        if (t == 0) g_offsets[0] = 0;
        __threadfence();
        __syncthreads();
        if (t == 0) g_scanflag = 1u;
        return;
    }
    if (b == 1) {
        float* sz = sy;
        for (int i = t; i < EMB; i += 512) sz[i] = z[i];
        __syncthreads();
        if (t < 64) {
            int j = t & 31;
            const float* W = (t < 32) ? (opW1 + 2 * EMB * NH1) : (prW1 + (1 + EMB) * NH1);
            float a0 = 0.f, a1 = 0.f, a2 = 0.f, a3 = 0.f;
            for (int k = 0; k < EMB; k += 4) {
                a0 += sz[k + 0] * W[(k + 0) * NH1 + j];
                a1 += sz[k + 1] * W[(k + 1) * NH1 + j];
                a2 += sz[k + 2] * W[(k + 2) * NH1 + j];
                a3 += sz[k + 3] * W[(k + 3) * NH1 + j];
            }
            float a = (a0 + a1) + (a2 + a3);
            if (t < 32) g_zop[j] = a;
            else        g_zpr[j] = a;
        }
        return;
    }
    if (b < 10) {
        // ---- W1 interleave, grouped-broadcast layout ----
        // g_w1i[kp*64 + h*32 + jl*4 + c] = opW1[(2*kp + (c&1))*32 + (4*jl + 2*h + (c>>1))]
        for (int idx = (b - 2) * 512 + t; idx < EMB * NH1; idx += 8 * 512) {
            int kp  = idx >> 6;
            int rem = idx & 63;
            int h   = (rem >> 5) & 1;
            int jl  = (rem >> 2) & 7;
            int c   = rem & 3;
            int e   = c & 1;
            int j   = 4 * jl + 2 * h + (c >> 1);
            g_w1i[idx] = opW1[(size_t)(2 * kp + e) * NH1 + j];
        }
        return;
    }
    if (b < 10 + 2 * nbY) {
        int bp = b - 10;
        int branch = (bp >= nbY) ? 1 : 0;
        int chunk = branch ? bp - nbY : bp;
        int w = t >> 5, j = t & 31;
        int d = chunk * 16 + w;

        for (int idx = t; idx < 16 * EMB; idx += 512) {
            int dd = chunk * 16 + (idx >> 8);
            sy[idx] = (dd < D) ? y[(size_t)dd * EMB + (idx & 255)] : 0.f;
        }
        const float* Wm = branch ? (prW1 + NH1) : (opW1 + EMB * NH1);
        float a0 = 0.f, a1 = 0.f;
        for (int kc = 0; kc < EMB; kc += 64) {
            __syncthreads();
            for (int idx = t; idx < 64 * NH1; idx += 512) sw[idx] = Wm[(size_t)kc * NH1 + idx];
            __syncthreads();
            const float* yr = sy + w * EMB + kc;
#pragma unroll
            for (int k = 0; k < 64; k += 2) {
                a0 += yr[k + 0] * sw[(k + 0) * NH1 + j];
                a1 += yr[k + 1] * sw[(k + 1) * NH1 + j];
            }
        }
        if (d < D) {
            float a = a0 + a1;
            if (!branch) g_yzop[d * NH1 + j]  = a;
            else         g_prpre[d * NH1 + j] = a;
        }
        return;
    }
    {
        int fb = b - (10 + 2 * nbY);
        if (t == 0) { while (g_scanflag == 0u) { __nanosleep(32); } }
        __syncthreads();
        __threadfence();
        int* soff = reinterpret_cast<int*>(sy);
        for (int i = t; i <= D; i += 512) soff[i] = g_offsets[i];
        __syncthreads();
        int i = fb * 512 + t;
        if (i < N) {
            int lo = 0, hi = D;
            while (lo < hi) {
                int mid = (lo + hi) >> 1;
                if (soff[mid + 1] <= i) lo = mid + 1; else hi = mid;
            }
            if (lo >= D) lo = D - 1;
            g_dagid[i] = lo;
        }
    }
}

// ================= persistent fused kernel: GEMM + softmax sum + prlvl + normalize =================
__global__ void __launch_bounds__(256, 2) k_ops(
    const float* __restrict__ x,
    const float* __restrict__ ob1,
    const float* __restrict__ W2, const float* __restrict__ b2,
    const float* __restrict__ W3, const float* __restrict__ b3,
    const float* __restrict__ msk,
    const float* __restrict__ prW1, const float* __restrict__ prb1,
    const float* __restrict__ prW2,
    const float* __restrict__ prb2, const float* __restrict__ prW3,
    const float* __restrict__ prb3, const float* __restrict__ pmsk,
    float* __restrict__ out, float* __restrict__ outp,
    int N, int W, int D, int nb)
{
    __shared__ float bufA[BM * SXW];       // 17.4 KB (aliased by sh in tail)
    __shared__ float bufB[BM * SXW];       // 17.4 KB (aliased by PR smem)
    __shared__ float swiA[(KC / 2) * 64];  // 4 KB
    __shared__ float swiB[(KC / 2) * 64];  // 4 KB
    __shared__ float sw2[NH1 * NH2];
    __shared__ float sb2[NH2], sw3[NH2];
    __shared__ float szop[NH1];            // z-part + b1 for op branch
    __shared__ float sb3v;
    __shared__ float swr[8];
    __shared__ int   s_last;

    int tid  = threadIdx.x;
    int w    = tid >> 5;
    int lane = tid & 31;
    int rl   = lane >> 3;       // row group 0..3
    int jl   = lane & 7;        // col group 0..7  -> cols 4jl..4jl+3
    int wrow = w * 16;          // 8 warps x 16 rows = 128
    int blk  = blockIdx.x;
    int grd  = gridDim.x;

    if (tid < 16) { sb2[tid] = b2[tid]; sw3[tid] = W3[tid]; }
    if (tid == 16) sb3v = b3[0];
    if (tid >= 32 && tid < 64) szop[tid - 32] = g_zop[tid - 32] + ob1[tid - 32];
    for (int i = tid; i < NH1 * NH2; i += 256) sw2[i] = W2[i];
    __syncthreads();

    const unsigned long long* w2_64 = reinterpret_cast<const unsigned long long*>(sw2);
    float e_save[8];
    int   ncl = N - 1;

    // ---------------- tile loop ----------------
    int ti = 0;
    for (int tile = blk; tile < nb; tile += grd, ti++) {
        int bm = tile * BM;

        {   // prologue: stage kc=0
            unsigned xa = smem_u32(bufA);
#pragma unroll
            for (int it = 0; it < 8; it++) {
                int fi = it * 256 + tid;
                int row = fi >> 4, c2 = fi & 15;
                int n = bm + row;
                const float* src = x + (size_t)min(n, ncl) * EMB + c2 * 2;
                unsigned dst = xa + (unsigned)(row * SXW + c2 * 2) * 4u;
                int sz = (n < N) ? 8 : 0;
                asm volatile("cp.async.ca.shared.global [%0], [%1], 8, %2;\n"
                             :: "r"(dst), "l"(src), "r"(sz));
            }
            unsigned wa = smem_u32(swiA);
            asm volatile("cp.async.ca.shared.global [%0], [%1], 16;\n"
                         :: "r"(wa + tid * 16u), "l"(g_w1i + tid * 4));
            asm volatile("cp.async.commit_group;\n");
        }

        unsigned long long acc[4][4];   // [row i][col c]
#pragma unroll
        for (int i = 0; i < 4; i++)
#pragma unroll
            for (int p = 0; p < 4; p++) acc[i][p] = 0ull;

        for (int ki = 0; ki < EMB / KC; ki++) {
            float* xb = (ki & 1) ? bufB : bufA;
            float* wb = (ki & 1) ? swiB : swiA;
            if (ki < EMB / KC - 1) {
                int kc = (ki + 1) * KC;
                float* xb2 = (ki & 1) ? bufA : bufB;
                float* wb2 = (ki & 1) ? swiA : swiB;
                unsigned xa = smem_u32(xb2);
#pragma unroll
                for (int it = 0; it < 8; it++) {
                    int fi = it * 256 + tid;
                    int row = fi >> 4, c2 = fi & 15;
                    int n = bm + row;
                    const float* src = x + (size_t)min(n, ncl) * EMB + kc + c2 * 2;
                    unsigned dst = xa + (unsigned)(row * SXW + c2 * 2) * 4u;
                    int sz = (n < N) ? 8 : 0;
                    asm volatile("cp.async.ca.shared.global [%0], [%1], 8, %2;\n"
                                 :: "r"(dst), "l"(src), "r"(sz));
                }
                unsigned wa = smem_u32(wb2);
                asm volatile("cp.async.ca.shared.global [%0], [%1], 16;\n"
                             :: "r"(wa + tid * 16u), "l"(g_w1i + kc * 32 + tid * 4));
                asm volatile("cp.async.commit_group;\n");
                asm volatile("cp.async.wait_group 1;\n");
            } else {
                asm volatile("cp.async.wait_group 0;\n");
            }
            __syncthreads();
#pragma unroll
            for (int kp = 0; kp < KC / 2; kp++) {
                // x: 4 rows (8-way broadcast LDS.64, 1 wavefront each)
                unsigned long long xk[4];
#pragma unroll
                for (int i = 0; i < 4; i++)
                    xk[i] = *reinterpret_cast<const unsigned long long*>(
                        &xb[(wrow + 4 * rl + i) * SXW + 2 * kp]);
                // w: cols 4jl..4jl+3 (grouped layout, conflict-free LDS.128, 1 wf each)
                ulonglong2 w01 = *reinterpret_cast<const ulonglong2*>(&wb[kp * 64 + jl * 4]);
                ulonglong2 w23 = *reinterpret_cast<const ulonglong2*>(&wb[kp * 64 + 32 + jl * 4]);
#pragma unroll
                for (int i = 0; i < 4; i++) {
                    ffma2(acc[i][0], xk[i], w01.x);
                    ffma2(acc[i][1], xk[i], w01.y);
                    ffma2(acc[i][2], xk[i], w23.x);
                    ffma2(acc[i][3], xk[i], w23.y);
                }
            }
            __syncthreads();
        }

        // reduce (even+odd k) and stage h-pre: lane covers rows wrow+4rl+i, cols 4jl+c
        float* sh = bufA;
#pragma unroll
        for (int i = 0; i < 4; i++) {
            int row = wrow + 4 * rl + i;
#pragma unroll
            for (int c = 0; c < 4; c++) {
                float2 f = unpack2(acc[i][c]);
                sh[row * SHP + 4 * jl + c] = f.x + f.y;
            }
        }
        __syncthreads();

        // tail: one row per thread (tid<128)
        float e = 0.f;
        int n = bm + tid;
        if (tid < BM && n < N) {
            int dag = g_dagid[n];
            const float4* yz4 = reinterpret_cast<const float4*>(&g_yzop[dag * NH1]);
            float h1[NH1];
#pragma unroll
            for (int q = 0; q < 8; q++) {
                float4 v = yz4[q];
                h1[q * 4 + 0] = fmaxf(sh[tid * SHP + q * 4 + 0] + v.x + szop[q * 4 + 0], 0.f);
                h1[q * 4 + 1] = fmaxf(sh[tid * SHP + q * 4 + 1] + v.y + szop[q * 4 + 1], 0.f);
                h1[q * 4 + 2] = fmaxf(sh[tid * SHP + q * 4 + 2] + v.z + szop[q * 4 + 2], 0.f);
                h1[q * 4 + 3] = fmaxf(sh[tid * SHP + q * 4 + 3] + v.w + szop[q * 4 + 3], 0.f);
            }
            unsigned long long a2[8];
#pragma unroll
            for (int p = 0; p < 8; p++) a2[p] = pack2(sb2[2 * p], sb2[2 * p + 1]);
#pragma unroll
            for (int j = 0; j < NH1; j++) {
                unsigned long long hd = pack2(h1[j], h1[j]);
#pragma unroll
                for (int p = 0; p < 8; p++) ffma2(a2[p], hd, w2_64[j * 8 + p]);
            }
            float logit = sb3v;
#pragma unroll
            for (int p = 0; p < 8; p++) {
                float2 f = unpack2(a2[p]);
                logit += fmaxf(f.x, 0.f) * sw3[2 * p] + fmaxf(f.y, 0.f) * sw3[2 * p + 1];
            }
            logit -= (1.f - msk[n]) * 1000.f;
            e = expf(logit);    // logits O(1); masked -> exp(-1000)=0
        }
        if (ti < 8) e_save[ti] = e;

        float bsum = e;
#pragma unroll
        for (int off = 16; off; off >>= 1) bsum += __shfl_down_sync(0xffffffffu, bsum, off);
        if (lane == 0) swr[w] = bsum;
        __syncthreads();
        if (tid == 0)
            g_partial[tile] = ((swr[0] + swr[1]) + (swr[2] + swr[3]))
                            + ((swr[4] + swr[5]) + (swr[6] + swr[7]));
        __syncthreads();
    }

    // ---------------- arrive; last block reduces ----------------
    __threadfence();
    if (tid == 0) {
        unsigned int prev = atomicAdd(&g_counter, 1u);
        s_last = (prev == (unsigned)grd - 1) ? 1 : 0;
    }
    __syncthreads();
    if (s_last) {
        __threadfence();
        const volatile float* vp = g_partial;
        float a = 0.f;
        for (int i = tid; i < nb; i += 256) a += vp[i];
#pragma unroll
        for (int off = 16; off; off >>= 1) a += __shfl_down_sync(0xffffffffu, a, off);
        if (lane == 0) swr[w] = a;
        __syncthreads();
        if (tid == 0) {
            g_inv = 1.0f / (((swr[0] + swr[1]) + (swr[2] + swr[3]))
                          + ((swr[4] + swr[5]) + (swr[6] + swr[7])));
            g_scanflag = 0u;   // reset for next graph replay
            __threadfence();
            g_relflag = 1u;
        }
    }

    // ---------------- prlvl: 4 dags per block ----------------
    int nbPR = (D + 3) / 4;
    if (blk < nbPR) {
        __syncthreads();
        float* spre = bufB;             // 128 (includes z-part + prb1)
        float* sr0  = bufB + 128;       // 32
        float* sW2p = bufB + 160;       // 512
        float* sb2p = bufB + 672;       // 16
        float* sW3p = bufB + 688;       // 16
        float* sb3p = bufB + 704;       // 1
        int dbase = blk * 4;
        int dl = tid >> 6, wk = tid & 63;
        int d = dbase + dl;

        if (tid < 4 * NH1) {
            int dd = dbase + (tid >> 5);
            int j = tid & 31;
            spre[tid] = ((dd < D) ? g_prpre[dbase * NH1 + tid] : 0.f) + g_zpr[j] + prb1[j];
        }
        if (tid >= 128 && tid < 160) sr0[tid - 128] = prW1[tid - 128];
        for (int i = tid; i < NH1 * NH2; i += 256) sW2p[i] = prW2[i];
        if (tid >= 160 && tid < 176) { sb2p[tid - 160] = prb2[tid - 160]; sW3p[tid - 160] = prW3[tid - 160]; }
        if (tid == 176) sb3p[0] = prb3[0];
        __syncthreads();

        const unsigned long long* w2p = reinterpret_cast<const unsigned long long*>(sW2p);
        float l = -1e30f;
        if (d < D && wk < W) {
            float lim = (float)(wk + 1);
            float h1[NH1];
#pragma unroll
            for (int j = 0; j < NH1; j++) h1[j] = fmaxf(spre[dl * NH1 + j] + lim * sr0[j], 0.f);
            unsigned long long a2[8];
#pragma unroll
            for (int p = 0; p < 8; p++) a2[p] = pack2(sb2p[2 * p], sb2p[2 * p + 1]);
#pragma unroll
            for (int j = 0; j < NH1; j++) {
                unsigned long long hd = pack2(h1[j], h1[j]);
#pragma unroll
                for (int p = 0; p < 8; p++) ffma2(a2[p], hd, w2p[j * 8 + p]);
            }
            float logit = sb3p[0];
#pragma unroll
            for (int p = 0; p < 8; p++) {
                float2 f = unpack2(a2[p]);
                logit += fmaxf(f.x, 0.f) * sW3p[2 * p] + fmaxf(f.y, 0.f) * sW3p[2 * p + 1];
            }
            l = logit - (1.f - pmsk[(size_t)d * W + wk]) * 1000.f;
        }
        float m = l;
#pragma unroll
        for (int off = 16; off; off >>= 1) m = fmaxf(m, __shfl_xor_sync(0xffffffffu, m, off));
        if (lane == 0) swr[w] = m;
        __syncthreads();
        m = fmaxf(swr[dl * 2], swr[dl * 2 + 1]);
        float e = (d < D && wk < W) ? expf(l - m) : 0.f;
        float s = e;
#pragma unroll
        for (int off = 16; off; off >>= 1) s += __shfl_xor_sync(0xffffffffu, s, off);
        __syncthreads();
        if (lane == 0) swr[w] = s;
        __syncthreads();
        s = swr[dl * 2] + swr[dl * 2 + 1];
        if (d < D && wk < W) outp[(size_t)d * W + wk] = e / s;
    }

    // ---------------- wait for g_inv, write normalized out from registers ----------------
    if (tid == 0) { while (g_relflag == 0u) { __nanosleep(64); } }
    __syncthreads();
    __threadfence();
    float inv = g_inv;
    ti = 0;
    for (int tile = blk; tile < nb; tile += grd, ti++) {
        int n = tile * BM + tid;
        if (ti < 8 && tid < BM && n < N) out[n] = e_save[ti] * inv;
    }
}

// ================= launch =================
extern "C" void kernel_launch(void* const* d_in, const int* in_sizes, int n_in,
                              void* d_out, int out_size) {
    int ix = 0; long long best = -1;
    for (int i = 0; i < n_in; i++)
        if ((long long)in_sizes[i] > best) { best = in_sizes[i]; ix = i; }

    const int*   num_ops = (const int*)d_in[0];
    const float* x    = (const float*)d_in[ix];
    const float* y    = (const float*)d_in[ix + 1];
    const float* z    = (const float*)d_in[ix + 2];
    const float* omsk = (const float*)d_in[ix + 3];
    const float* pmsk = (const float*)d_in[ix + 4];
    const float* oW1  = (const float*)d_in[ix + 5];
    const float* ob1  = (const float*)d_in[ix + 6];
    const float* oW2  = (const float*)d_in[ix + 7];
    const float* ob2  = (const float*)d_in[ix + 8];
    const float* oW3  = (const float*)d_in[ix + 9];
    const float* ob3  = (const float*)d_in[ix + 10];
    const float* pW1  = (const float*)d_in[ix + 11];
    const float* pb1  = (const float*)d_in[ix + 12];
    const float* pW2  = (const float*)d_in[ix + 13];
    const float* pb2  = (const float*)d_in[ix + 14];
    const float* pW3  = (const float*)d_in[ix + 15];
    const float* pb3  = (const float*)d_in[ix + 16];

    int N = in_sizes[ix] / EMB;
    int D = in_sizes[ix + 1] / EMB;
    int W = in_sizes[ix + 4] / D;

    float* out  = (float*)d_out;
    float* outp = out + N;

    int nbY = (D + 15) / 16;
    int nbF = (N + 511) / 512;
    int nb  = (N + BM - 1) / BM;

    k_pre<<<10 + 2 * nbY + nbF, 512>>>(num_ops, z, y, oW1, pW1, D, N, nbY, nbF);
    k_ops<<<GRID_OPS, 256>>>(x, ob1, oW2, ob2, oW3, ob3, omsk,
                             pW1, pb1, pW2, pb2, pW3, pb3, pmsk,
                             out, outp, N, W, D, nb);
}

// round 15
// speedup vs baseline: 1.0550x; 1.0550x over previous
#include <cuda_runtime.h>
#include <math.h>

#define EMB 256
#define NH1 32
#define NH2 16
#define MAXDAGS 1024
#define MAXOPS  102400
#define BM 192
#define KC 16
#define SXW 20          // x row stride (floats): rows 16B-aligned
#define SHP 34          // h-pre row stride (even for u64 stores)
#define GRID_OPS 296

// dynamic smem layout (floats)
#define SM_XA 0
#define SM_XB 3840
#define SM_WA 7680
#define SM_WB 8320
#define SM_W2 8960
#define SM_TOT 9472     // 37888 bytes

// ---------------- scratch (device globals; no allocation allowed) ----------------
__device__ int   g_offsets[MAXDAGS + 1];
__device__ int   g_dagid[MAXOPS];
__device__ float g_yzop[MAXDAGS * NH1];
__device__ float g_prpre[MAXDAGS * NH1];
__device__ float g_zop[NH1];
__device__ float g_zpr[NH1];
__device__ float g_partial[1024];
__device__ float g_w1i[16 * 8 * 80];     // [stage][kp][pad-swizzled 80]
__device__ unsigned int g_tile;
__device__ volatile unsigned int g_scanflag;

// ---------------- f32x2 helpers ----------------
__device__ __forceinline__ void ffma2(unsigned long long& d, unsigned long long a, unsigned long long b) {
    asm("fma.rn.f32x2 %0, %1, %2, %0;" : "+l"(d) : "l"(a), "l"(b));
}
__device__ __forceinline__ unsigned long long pack2(float x, float y) {
    unsigned long long r;
    asm("mov.b64 %0, {%1,%2};" : "=l"(r) : "f"(x), "f"(y));
    return r;
}
__device__ __forceinline__ float2 unpack2(unsigned long long v) {
    float2 r;
    asm("mov.b64 {%0,%1}, %2;" : "=f"(r.x), "=f"(r.y) : "l"(v));
    return r;
}
__device__ __forceinline__ unsigned int smem_u32(const void* p) {
    return (unsigned int)__cvta_generic_to_shared(p);
}

// ================= k_pre: ALL preprocessing in one wide parallel launch =================
__global__ void __launch_bounds__(512) k_pre(
    const int* __restrict__ num_ops, const float* __restrict__ z,
    const float* __restrict__ y,
    const float* __restrict__ opW1, const float* __restrict__ prW1,
    int D, int N, int nbY, int nbF)
{
    __shared__ float sy[16 * EMB];
    __shared__ float sw[64 * NH1];
    int t = threadIdx.x;
    int b = blockIdx.x;

    if (b == 0) {
        if (t == 0) g_tile = 0u;
        int* s = reinterpret_cast<int*>(sy);
        for (int i = t; i < 1024; i += 512) s[i] = (i < D) ? num_ops[i] : 0;
        __syncthreads();
        for (int off = 1; off < 1024; off <<= 1) {
            int i0 = t, i1 = t + 512;
            int v0 = (i0 >= off) ? s[i0 - off] : 0;
            int v1 = (i1 >= off) ? s[i1 - off] : 0;
            __syncthreads();
            s[i0] += v0; s[i1] += v1;
            __syncthreads();
        }
        for (int i = t; i < 1024; i += 512) g_offsets[i + 1] = s[i];
        if (t == 0) g_offsets[0] = 0;
        __threadfence();
        __syncthreads();
        if (t == 0) g_scanflag = 1u;
        return;
    }
    if (b == 1) {
        float* sz = sy;
        for (int i = t; i < EMB; i += 512) sz[i] = z[i];
        __syncthreads();
        if (t < 64) {
            int j = t & 31;
            const float* W = (t < 32) ? (opW1 + 2 * EMB * NH1) : (prW1 + (1 + EMB) * NH1);
            float a0 = 0.f, a1 = 0.f, a2 = 0.f, a3 = 0.f;
            for (int k = 0; k < EMB; k += 4) {
                a0 += sz[k + 0] * W[(k + 0) * NH1 + j];
                a1 += sz[k + 1] * W[(k + 1) * NH1 + j];
                a2 += sz[k + 2] * W[(k + 2) * NH1 + j];
                a3 += sz[k + 3] * W[(k + 3) * NH1 + j];
            }
            float a = (a0 + a1) + (a2 + a3);
            if (t < 32) g_zop[j] = a;
            else        g_zpr[j] = a;
        }
        return;
    }
    if (b < 10) {
        // pad-swizzled W1: g_w1i[s*640 + kp*80 + jg*20 + 2c + e] = opW1[(16s+2kp+e)*32 + 8jg+c]
        for (int m = (b - 2) * 512 + t; m < EMB * NH1; m += 8 * 512) {
            int k = m >> 5, j = m & 31;
            int s = k >> 4, kk = k & 15;
            int kp = kk >> 1, e = kk & 1;
            int jg = j >> 3, c = j & 7;
            g_w1i[s * 640 + kp * 80 + jg * 20 + 2 * c + e] = opW1[m];
        }
        return;
    }
    if (b < 10 + 2 * nbY) {
        int bp = b - 10;
        int branch = (bp >= nbY) ? 1 : 0;
        int chunk = branch ? bp - nbY : bp;
        int w = t >> 5, j = t & 31;
        int d = chunk * 16 + w;

        for (int idx = t; idx < 16 * EMB; idx += 512) {
            int dd = chunk * 16 + (idx >> 8);
            sy[idx] = (dd < D) ? y[(size_t)dd * EMB + (idx & 255)] : 0.f;
        }
        const float* Wm = branch ? (prW1 + NH1) : (opW1 + EMB * NH1);
        float a0 = 0.f, a1 = 0.f;
        for (int kc = 0; kc < EMB; kc += 64) {
            __syncthreads();
            for (int idx = t; idx < 64 * NH1; idx += 512) sw[idx] = Wm[(size_t)kc * NH1 + idx];
            __syncthreads();
            const float* yr = sy + w * EMB + kc;
#pragma unroll
            for (int k = 0; k < 64; k += 2) {
                a0 += yr[k + 0] * sw[(k + 0) * NH1 + j];
                a1 += yr[k + 1] * sw[(k + 1) * NH1 + j];
            }
        }
        if (d < D) {
            float a = a0 + a1;
            if (!branch) g_yzop[d * NH1 + j]  = a;
            else         g_prpre[d * NH1 + j] = a;
        }
        return;
    }
    {
        int fb = b - (10 + 2 * nbY);
        if (t == 0) { while (g_scanflag == 0u) { __nanosleep(32); } }
        __syncthreads();
        __threadfence();
        int* soff = reinterpret_cast<int*>(sy);
        for (int i = t; i <= D; i += 512) soff[i] = g_offsets[i];
        __syncthreads();
        int i = fb * 512 + t;
        if (i < N) {
            int lo = 0, hi = D;
            while (lo < hi) {
                int mid = (lo + hi) >> 1;
                if (soff[mid + 1] <= i) lo = mid + 1; else hi = mid;
            }
            if (lo >= D) lo = D - 1;
            g_dagid[i] = lo;
        }
    }
}

// ================= k_ops: GEMM + MLP tail + exp, per-tile partial sums (NO cross-block sync) =================
__global__ void __launch_bounds__(128) k_ops(
    const float* __restrict__ x,
    const float* __restrict__ ob1,
    const float* __restrict__ W2, const float* __restrict__ b2,
    const float* __restrict__ W3, const float* __restrict__ b3,
    const float* __restrict__ msk,
    float* __restrict__ out,
    int N, int nb)
{
    extern __shared__ float smp[];
    __shared__ float sb2[NH2], sw3[NH2], szop[NH1];
    __shared__ float sb3v;
    __shared__ float swr[4];
    __shared__ int   s_tile;

    int tid  = threadIdx.x;
    int w    = tid >> 5;
    int lane = tid & 31;
    int rg   = lane & 7;       // row group within warp rows
    int jg   = lane >> 3;      // col group: cols 8jg..8jg+7
    int wrow = w * 48;         // 4 warps x 48 rows = 192
    int ncl  = N - 1;

    if (tid < 16) { sb2[tid] = b2[tid]; sw3[tid] = W3[tid]; }
    if (tid == 16) sb3v = b3[0];
    if (tid >= 32 && tid < 64) szop[tid - 32] = g_zop[tid - 32] + ob1[tid - 32];
    for (int i = tid; i < NH1 * NH2; i += 128) smp[SM_W2 + i] = W2[i];
    __syncthreads();

    const unsigned long long* w2_64 = reinterpret_cast<const unsigned long long*>(smp + SM_W2);

    for (;;) {
        // block-uniform tile acquisition (R13/R14 bug: per-thread atomicAdd)
        if (tid == 0) s_tile = (int)atomicAdd(&g_tile, 1u);
        __syncthreads();
        int tile = s_tile;
        if (tile >= nb) break;
        int bm = tile * BM;

        {   // prologue: stage kc=0 into A
            unsigned xa = smem_u32(smp + SM_XA);
#pragma unroll
            for (int it = 0; it < 6; it++) {
                int idx = it * 128 + tid;          // 0..767
                int row = idx >> 2, c4 = idx & 3;
                int n = bm + row;
                const float* src = x + (size_t)min(n, ncl) * EMB + c4 * 4;
                unsigned dst = xa + (unsigned)(row * SXW + c4 * 4) * 4u;
                int sz = (n < N) ? 16 : 0;
                asm volatile("cp.async.ca.shared.global [%0], [%1], 16, %2;\n"
                             :: "r"(dst), "l"(src), "r"(sz));
            }
            unsigned wa = smem_u32(smp + SM_WA);
#pragma unroll
            for (int it = 0; it < 2; it++) {
                int idx = it * 128 + tid;
                if (idx < 160)
                    asm volatile("cp.async.ca.shared.global [%0], [%1], 16;\n"
                                 :: "r"(wa + idx * 16u), "l"(g_w1i + idx * 4));
            }
            asm volatile("cp.async.commit_group;\n");
        }

        unsigned long long acc[6][8];
#pragma unroll
        for (int i = 0; i < 6; i++)
#pragma unroll
            for (int c = 0; c < 8; c++) acc[i][c] = 0ull;

        for (int ki = 0; ki < EMB / KC; ki++) {
            const float* xb = smp + ((ki & 1) ? SM_XB : SM_XA);
            const float* wb = smp + ((ki & 1) ? SM_WB : SM_WA);
            if (ki < EMB / KC - 1) {
                int kc = (ki + 1) * KC;
                unsigned xa = smem_u32(smp + ((ki & 1) ? SM_XA : SM_XB));
                unsigned wa = smem_u32(smp + ((ki & 1) ? SM_WA : SM_WB));
#pragma unroll
                for (int it = 0; it < 6; it++) {
                    int idx = it * 128 + tid;
                    int row = idx >> 2, c4 = idx & 3;
                    int n = bm + row;
                    const float* src = x + (size_t)min(n, ncl) * EMB + kc + c4 * 4;
                    unsigned dst = xa + (unsigned)(row * SXW + c4 * 4) * 4u;
                    int sz = (n < N) ? 16 : 0;
                    asm volatile("cp.async.ca.shared.global [%0], [%1], 16, %2;\n"
                                 :: "r"(dst), "l"(src), "r"(sz));
                }
#pragma unroll
                for (int it = 0; it < 2; it++) {
                    int idx = it * 128 + tid;
                    if (idx < 160)
                        asm volatile("cp.async.ca.shared.global [%0], [%1], 16;\n"
                                     :: "r"(wa + idx * 16u), "l"(g_w1i + (ki + 1) * 640 + idx * 4));
                }
                asm volatile("cp.async.commit_group;\n");
                asm volatile("cp.async.wait_group 1;\n");
            } else {
                asm volatile("cp.async.wait_group 0;\n");
            }
            __syncthreads();
#pragma unroll
            for (int kp = 0; kp < KC / 2; kp++) {
                unsigned long long xk[6];
#pragma unroll
                for (int i = 0; i < 6; i++)
                    xk[i] = *reinterpret_cast<const unsigned long long*>(
                        &xb[(wrow + rg + 8 * i) * SXW + 2 * kp]);
                const float* wp = wb + kp * 80 + jg * 20;
                ulonglong2 wq0 = *reinterpret_cast<const ulonglong2*>(wp);
                ulonglong2 wq1 = *reinterpret_cast<const ulonglong2*>(wp + 4);
                ulonglong2 wq2 = *reinterpret_cast<const ulonglong2*>(wp + 8);
                ulonglong2 wq3 = *reinterpret_cast<const ulonglong2*>(wp + 12);
#pragma unroll
                for (int i = 0; i < 6; i++) {
                    ffma2(acc[i][0], xk[i], wq0.x);
                    ffma2(acc[i][1], xk[i], wq0.y);
                    ffma2(acc[i][2], xk[i], wq1.x);
                    ffma2(acc[i][3], xk[i], wq1.y);
                    ffma2(acc[i][4], xk[i], wq2.x);
                    ffma2(acc[i][5], xk[i], wq2.y);
                    ffma2(acc[i][6], xk[i], wq3.x);
                    ffma2(acc[i][7], xk[i], wq3.y);
                }
            }
            __syncthreads();
        }

        // reduce (even+odd k) and stage h-pre into XA/XB region
        float* sh = smp + SM_XA;
#pragma unroll
        for (int i = 0; i < 6; i++) {
            int row = wrow + rg + 8 * i;
#pragma unroll
            for (int c2 = 0; c2 < 4; c2++) {
                float2 f0 = unpack2(acc[i][2 * c2]);
                float2 f1 = unpack2(acc[i][2 * c2 + 1]);
                *reinterpret_cast<unsigned long long*>(&sh[row * SHP + jg * 8 + 2 * c2]) =
                    pack2(f0.x + f0.y, f1.x + f1.y);
            }
        }
        __syncthreads();

        // tail: up to 2 rows per thread
        float bsum = 0.f;
#pragma unroll
        for (int rr = 0; rr < 2; rr++) {
            int r = tid + rr * 128;
            int n = bm + r;
            if (r < BM && n < N) {
                int dag = g_dagid[n];
                const float4* yz4 = reinterpret_cast<const float4*>(&g_yzop[dag * NH1]);
                float h1[NH1];
#pragma unroll
                for (int q = 0; q < 8; q++) {
                    float4 v = yz4[q];
                    h1[q * 4 + 0] = fmaxf(sh[r * SHP + q * 4 + 0] + v.x + szop[q * 4 + 0], 0.f);
                    h1[q * 4 + 1] = fmaxf(sh[r * SHP + q * 4 + 1] + v.y + szop[q * 4 + 1], 0.f);
                    h1[q * 4 + 2] = fmaxf(sh[r * SHP + q * 4 + 2] + v.z + szop[q * 4 + 2], 0.f);
                    h1[q * 4 + 3] = fmaxf(sh[r * SHP + q * 4 + 3] + v.w + szop[q * 4 + 3], 0.f);
                }
                unsigned long long a2[8];
#pragma unroll
                for (int p = 0; p < 8; p++) a2[p] = pack2(sb2[2 * p], sb2[2 * p + 1]);
#pragma unroll
                for (int j = 0; j < NH1; j++) {
                    unsigned long long hd = pack2(h1[j], h1[j]);
#pragma unroll
                    for (int p = 0; p < 8; p++) ffma2(a2[p], hd, w2_64[j * 8 + p]);
                }
                float logit = sb3v;
#pragma unroll
                for (int p = 0; p < 8; p++) {
                    float2 f = unpack2(a2[p]);
                    logit += fmaxf(f.x, 0.f) * sw3[2 * p] + fmaxf(f.y, 0.f) * sw3[2 * p + 1];
                }
                logit -= (1.f - msk[n]) * 1000.f;
                float e = expf(logit);   // logits O(1); masked -> exp(-1000)=0
                out[n] = e;              // unnormalized; scaled in k_fin
                bsum += e;
            }
        }
#pragma unroll
        for (int off = 16; off; off >>= 1) bsum += __shfl_down_sync(0xffffffffu, bsum, off);
        if (lane == 0) swr[w] = bsum;
        __syncthreads();
        if (tid == 0)
            g_partial[tile] = (swr[0] + swr[1]) + (swr[2] + swr[3]);
        __syncthreads();   // protects smem (sh/swr/s_tile) before next tile
    }
}

// ================= k_fin: blocks [0,nbPR) = prlvl; rest = deterministic sum + normalize =================
__global__ void __launch_bounds__(256) k_fin(
    const float* __restrict__ prW1, const float* __restrict__ prb1,
    const float* __restrict__ prW2, const float* __restrict__ prb2,
    const float* __restrict__ prW3, const float* __restrict__ prb3,
    const float* __restrict__ pmsk,
    float* __restrict__ out, float* __restrict__ outp,
    int N, int W, int D, int nb, int nbPR)
{
    __shared__ float sred[256];
    __shared__ float spre[128], sr0[NH1], sW2p[NH1 * NH2], sb2p[NH2], sW3p[NH2];
    __shared__ float sb3p;
    __shared__ float swr[8];
    int tid = threadIdx.x;
    int blk = blockIdx.x;
    if (blk == 0 && tid == 0) g_scanflag = 0u;   // reset for next replay

    if (blk >= nbPR) {
        // deterministic fixed-order global sum (identical in every block)
        float a = 0.f;
        for (int i = tid; i < nb; i += 256) a += g_partial[i];
        sred[tid] = a;
        __syncthreads();
        for (int off = 128; off; off >>= 1) {
            if (tid < off) sred[tid] += sred[tid + off];
            __syncthreads();
        }
        float inv = 1.0f / sred[0];
        int i4 = (blk - nbPR) * 256 + tid;
        if (i4 < (N >> 2)) {
            float4* o4 = reinterpret_cast<float4*>(out);
            float4 v = o4[i4];
            v.x *= inv; v.y *= inv; v.z *= inv; v.w *= inv;
            o4[i4] = v;
        }
        if (blk == nbPR && tid == 0)
            for (int r = (N & ~3); r < N; r++) out[r] *= inv;
        return;
    }

    // ---- prlvl: 4 dags per block ----
    int dbase = blk * 4;
    int dl = tid >> 6, wk = tid & 63;
    int lane = tid & 31, w8 = tid >> 5;
    int d = dbase + dl;

    if (tid < 128) {
        int dd = dbase + (tid >> 5);
        int j = tid & 31;
        spre[tid] = ((dd < D) ? g_prpre[dbase * NH1 + tid] : 0.f) + g_zpr[j] + prb1[j];
    }
    if (tid >= 128 && tid < 160) sr0[tid - 128] = prW1[tid - 128];
    for (int i = tid; i < NH1 * NH2; i += 256) sW2p[i] = prW2[i];
    if (tid >= 160 && tid < 176) { sb2p[tid - 160] = prb2[tid - 160]; sW3p[tid - 160] = prW3[tid - 160]; }
    if (tid == 176) sb3p = prb3[0];
    __syncthreads();

    const unsigned long long* w2p = reinterpret_cast<const unsigned long long*>(sW2p);
    float l = -1e30f;
    if (d < D && wk < W) {
        float lim = (float)(wk + 1);
        float h1[NH1];
#pragma unroll
        for (int j = 0; j < NH1; j++) h1[j] = fmaxf(spre[dl * NH1 + j] + lim * sr0[j], 0.f);
        unsigned long long a2[8];
#pragma unroll
        for (int p = 0; p < 8; p++) a2[p] = pack2(sb2p[2 * p], sb2p[2 * p + 1]);
#pragma unroll
        for (int j = 0; j < NH1; j++) {
            unsigned long long hd = pack2(h1[j], h1[j]);
#pragma unroll
            for (int p = 0; p < 8; p++) ffma2(a2[p], hd, w2p[j * 8 + p]);
        }
        float logit = sb3p;
#pragma unroll
        for (int p = 0; p < 8; p++) {
            float2 f = unpack2(a2[p]);
            logit += fmaxf(f.x, 0.f) * sW3p[2 * p] + fmaxf(f.y, 0.f) * sW3p[2 * p + 1];
        }
        l = logit - (1.f - pmsk[(size_t)d * W + wk]) * 1000.f;
    }
    float m = l;
#pragma unroll
    for (int off = 16; off; off >>= 1) m = fmaxf(m, __shfl_xor_sync(0xffffffffu, m, off));
    if (lane == 0) swr[w8] = m;
    __syncthreads();
    m = fmaxf(swr[dl * 2], swr[dl * 2 + 1]);
    float e = (d < D && wk < W) ? expf(l - m) : 0.f;
    float s = e;
#pragma unroll
    for (int off = 16; off; off >>= 1) s += __shfl_xor_sync(0xffffffffu, s, off);
    __syncthreads();
    if (lane == 0) swr[w8] = s;
    __syncthreads();
    s = swr[dl * 2] + swr[dl * 2 + 1];
    if (d < D && wk < W) outp[(size_t)d * W + wk] = e / s;
}

// ================= launch =================
extern "C" void kernel_launch(void* const* d_in, const int* in_sizes, int n_in,
                              void* d_out, int out_size) {
    int ix = 0; long long best = -1;
    for (int i = 0; i < n_in; i++)
        if ((long long)in_sizes[i] > best) { best = in_sizes[i]; ix = i; }

    const int*   num_ops = (const int*)d_in[0];
    const float* x    = (const float*)d_in[ix];
    const float* y    = (const float*)d_in[ix + 1];
    const float* z    = (const float*)d_in[ix + 2];
    const float* omsk = (const float*)d_in[ix + 3];
    const float* pmsk = (const float*)d_in[ix + 4];
    const float* oW1  = (const float*)d_in[ix + 5];
    const float* ob1  = (const float*)d_in[ix + 6];
    const float* oW2  = (const float*)d_in[ix + 7];
    const float* ob2  = (const float*)d_in[ix + 8];
    const float* oW3  = (const float*)d_in[ix + 9];
    const float* ob3  = (const float*)d_in[ix + 10];
    const float* pW1  = (const float*)d_in[ix + 11];
    const float* pb1  = (const float*)d_in[ix + 12];
    const float* pW2  = (const float*)d_in[ix + 13];
    const float* pb2  = (const float*)d_in[ix + 14];
    const float* pW3  = (const float*)d_in[ix + 15];
    const float* pb3  = (const float*)d_in[ix + 16];

    int N = in_sizes[ix] / EMB;
    int D = in_sizes[ix + 1] / EMB;
    int W = in_sizes[ix + 4] / D;

    float* out  = (float*)d_out;
    float* outp = out + N;

    int nbY    = (D + 15) / 16;
    int nbF    = (N + 511) / 512;
    int nb     = (N + BM - 1) / BM;
    int nbPR   = (D + 3) / 4;
    int nbNorm = (N / 4 + 255) / 256 + 1;
    int smem_bytes = SM_TOT * 4;

    cudaFuncSetAttribute(k_ops, cudaFuncAttributeMaxDynamicSharedMemorySize, smem_bytes);

    k_pre<<<10 + 2 * nbY + nbF, 512>>>(num_ops, z, y, oW1, pW1, D, N, nbY, nbF);
    k_ops<<<GRID_OPS, 128, smem_bytes>>>(x, ob1, oW2, ob2, oW3, ob3, omsk, out, N, nb);
    k_fin<<<nbPR + nbNorm, 256>>>(pW1, pb1, pW2, pb2, pW3, pb3, pmsk,
                                  out, outp, N, W, D, nb, nbPR);
}